// round 7
// baseline (speedup 1.0000x reference)
#include <cuda_runtime.h>
#include <cuda_bf16.h>

// CustomEmbedding: out[t, :] = sin((id/1000)*(i+1)) if id<1000 else weight[id, :]
// Tokens: 8*4096 = 32768, DIM = 512 floats = 128 float4 per row.
// One WARP per FOUR tokens:
//   - all 4 ids fetched with a single int4 LDG (broadcast within warp)
//   - 16 independent row LDG.128s front-batched (fast path)
//   - 16 streaming STG.128s (evict-first keeps weight table L2-resident)
// 256-thread block = 8 warps = 32 tokens; grid = 1024 blocks = ONE wave.

#define DIM4 128            // 512 floats / 4

__device__ __forceinline__ float4 sin4(float s, int jj) {
    float b = (float)(jj * 4);
    float4 v;
    v.x = sinf(s * (b + 1.0f));
    v.y = sinf(s * (b + 2.0f));
    v.z = sinf(s * (b + 3.0f));
    v.w = sinf(s * (b + 4.0f));
    return v;
}

__global__ void __launch_bounds__(256)
embed_kernel(const int4* __restrict__ x4,    // token ids, viewed as quads
             const float4* __restrict__ w,   // [VOCAB, DIM4]
             float4* __restrict__ out,       // [N, DIM4]
             int n_quads)
{
    int warp = (blockIdx.x * blockDim.x + threadIdx.x) >> 5;  // global warp = quad idx
    int j    = threadIdx.x & 31;                              // lane -> float4 idx base
    if (warp >= n_quads) return;

    int4 ids = __ldg(x4 + warp);        // one 16B load, broadcast across warp
    int  t0  = warp * 4;

    const float4* r0 = w + (size_t)ids.x * DIM4;
    const float4* r1 = w + (size_t)ids.y * DIM4;
    const float4* r2 = w + (size_t)ids.z * DIM4;
    const float4* r3 = w + (size_t)ids.w * DIM4;

    float4 v[4][4];

    bool all_reg = (ids.x >= 1000) & (ids.y >= 1000) &
                   (ids.z >= 1000) & (ids.w >= 1000);

    if (all_reg) {
        // fast path (~92% of warps): 16 independent loads, front-batched
        #pragma unroll
        for (int k = 0; k < 4; k++) {
            v[0][k] = __ldg(r0 + j + 32 * k);
            v[1][k] = __ldg(r1 + j + 32 * k);
            v[2][k] = __ldg(r2 + j + 32 * k);
            v[3][k] = __ldg(r3 + j + 32 * k);
        }
    } else {
        int idv[4] = {ids.x, ids.y, ids.z, ids.w};
        #pragma unroll
        for (int q = 0; q < 4; q++) {
            if (idv[q] < 1000) {
                float s = (float)idv[q] * 1e-3f;
                #pragma unroll
                for (int k = 0; k < 4; k++)
                    v[q][k] = sin4(s, j + 32 * k);
            } else {
                const float4* r = w + (size_t)idv[q] * DIM4;
                #pragma unroll
                for (int k = 0; k < 4; k++)
                    v[q][k] = __ldg(r + j + 32 * k);
            }
        }
    }

    #pragma unroll
    for (int q = 0; q < 4; q++) {
        float4* o = out + (size_t)(t0 + q) * DIM4;
        #pragma unroll
        for (int k = 0; k < 4; k++)
            __stcs(o + j + 32 * k, v[q][k]);
    }
}

extern "C" void kernel_launch(void* const* d_in, const int* in_sizes, int n_in,
                              void* d_out, int out_size)
{
    // metadata order: x (int32), weight (float32), num_value (int32), is_num (bool)
    const int4*   x4 = (const int4*)d_in[0];
    const float4* w  = (const float4*)d_in[1];
    float4*      out = (float4*)d_out;

    int n_tokens = in_sizes[0];           // 32768 (multiple of 4)
    int n_quads  = n_tokens / 4;          // 8192 warps
    int blocks   = (n_quads * 32 + 255) / 256;   // 1024 -> exactly one wave

    embed_kernel<<<blocks, 256>>>(x4, w, out, n_quads);
}